// round 14
// baseline (speedup 1.0000x reference)
#include <cuda_runtime.h>
#include <cuda_fp16.h>
#include <cstdint>

#define BB 2
#define TT 2048
#define CC 2048
#define HH 16
#define HD 128
#define M1 (BB*TT)      // 4096
#define N1 (3*CC)       // 6144
#define K1 CC           // 2048

// ---------------- device scratch ----------------
__device__ __half g_x16[M1*K1];
__device__ __half g_wa16[N1*K1];
__device__ __half g_wp16[CC*CC];
__device__ __half g_q16[BB*HH*TT*HD];
__device__ __half g_k16[BB*HH*TT*HD];
__device__ __half g_v16[BB*HH*TT*HD];
__device__ __half g_y16[M1*CC];

// ---------------- helpers ----------------
__device__ __forceinline__ uint32_t smem_u32(const void* p) {
    return (uint32_t)__cvta_generic_to_shared(p);
}
__device__ __forceinline__ void ldsm_x4(uint32_t& r0, uint32_t& r1,
                                        uint32_t& r2, uint32_t& r3, uint32_t addr) {
    asm volatile("ldmatrix.sync.aligned.m8n8.x4.shared.b16 {%0,%1,%2,%3}, [%4];\n"
                 : "=r"(r0), "=r"(r1), "=r"(r2), "=r"(r3) : "r"(addr));
}
__device__ __forceinline__ void ldsm_x4t(uint32_t& r0, uint32_t& r1,
                                         uint32_t& r2, uint32_t& r3, uint32_t addr) {
    asm volatile("ldmatrix.sync.aligned.m8n8.x4.trans.shared.b16 {%0,%1,%2,%3}, [%4];\n"
                 : "=r"(r0), "=r"(r1), "=r"(r2), "=r"(r3) : "r"(addr));
}
__device__ __forceinline__ void mma_fp16(float* c,
                                         uint32_t a0, uint32_t a1, uint32_t a2, uint32_t a3,
                                         uint32_t b0, uint32_t b1) {
    asm volatile("mma.sync.aligned.m16n8k16.row.col.f32.f16.f16.f32 "
                 "{%0,%1,%2,%3}, {%4,%5,%6,%7}, {%8,%9}, {%0,%1,%2,%3};\n"
                 : "+f"(c[0]), "+f"(c[1]), "+f"(c[2]), "+f"(c[3])
                 : "r"(a0), "r"(a1), "r"(a2), "r"(a3), "r"(b0), "r"(b1));
}
__device__ __forceinline__ void cp16(uint32_t saddr, const void* g) {
    asm volatile("cp.async.cg.shared.global [%0], [%1], 16;\n" :: "r"(saddr), "l"(g));
}
#define CP_COMMIT() asm volatile("cp.async.commit_group;\n" ::: "memory")
#define CP_WAIT(N)  asm volatile("cp.async.wait_group %0;\n" :: "n"(N) : "memory")

// ---------------- fused fp32 -> fp16 cast (all three inputs) ----------------
#define XN4  (M1*K1/4)
#define WAN4 (N1*K1/4)
#define WPN4 (CC*CC/4)

__global__ void split_all(const float* __restrict__ x, const float* __restrict__ wa,
                          const float* __restrict__ wp,
                          uint2* __restrict__ ox, uint2* __restrict__ owa,
                          uint2* __restrict__ owp)
{
    int i = blockIdx.x * blockDim.x + threadIdx.x;
    const float* src;
    uint2* dst;
    int j;
    if (i < XN4)                 { src = x;  dst = ox;  j = i; }
    else if (i < XN4 + WAN4)     { src = wa; dst = owa; j = i - XN4; }
    else if (i < XN4+WAN4+WPN4)  { src = wp; dst = owp; j = i - XN4 - WAN4; }
    else return;
    float4 v = ((const float4*)src)[j];
    __half2 h0 = __floats2half2_rn(v.x, v.y);
    __half2 h1 = __floats2half2_rn(v.z, v.w);
    uint2 o;
    o.x = *(uint32_t*)&h0;
    o.y = *(uint32_t*)&h1;
    dst[j] = o;
}

// ---------------------------------------------------------------------------
// QKV GEMM, ratio-4: 4 warps (2x2), warp tile 64x64, block 128x128x64,
// 2-stage cp.async, one sync per chunk, prefetch interleaved.
// Register-lean: all 4 A-frags preloaded per ks; B loaded per 16-row group.
// Epilogue: q scaled by scale*log2e (fp16); k,v fp16; [B,H,T,HD] scatter.
// ---------------------------------------------------------------------------
#define Q_GSK 72
#define Q_GTSZ (128*Q_GSK)
#define Q_GSTG (2*Q_GTSZ)             // 18432 halves = 36864 B per stage
#define Q_SMEM (2*Q_GSTG*2)           // 73728 B

__global__ __launch_bounds__(128, 3)
void gemm_qkv64(const __half* __restrict__ A, const __half* __restrict__ W,
                __half* __restrict__ q16, __half* __restrict__ k16,
                __half* __restrict__ v16)
{
    extern __shared__ __half gs[];
    const int Kd   = K1;
    const int tid  = threadIdx.x;
    const int lane = tid & 31;
    const int wid  = tid >> 5;      // 0..3
    const int wm   = wid >> 1;      // 0..1
    const int wn   = wid & 1;       // 0..1
    const int m0   = blockIdx.y * 128;
    const int n0   = blockIdx.x * 128;

    float c[4][8][4];
#pragma unroll
    for (int mt = 0; mt < 4; mt++)
#pragma unroll
        for (int nt = 0; nt < 8; nt++)
#pragma unroll
            for (int r = 0; r < 4; r++) c[mt][nt][r] = 0.0f;

    const int lm_row = lane & 15;
    const int lm_kc  = (lane >> 4) << 3;

    // one cp16 of 16-per-chunk pattern (128 threads)
    auto issue_one = [&](int s, int kt, int it) {
        __half* stg = gs + s * Q_GSTG;
        int g   = tid + it * 128;       // 0..2047
        int sel = g >> 10;              // 0=A, 1=W
        int rem = g & 1023;
        int row = rem >> 3;             // 0..127
        int col = (rem & 7) * 8;        // 0..56
        const __half* src = sel ? (W + (size_t)(n0 + row) * Kd + kt + col)
                                : (A + (size_t)(m0 + row) * Kd + kt + col);
        cp16(smem_u32(stg + sel * Q_GTSZ + row * Q_GSK + col), src);
    };

    const int nk = Kd / 64;
#pragma unroll
    for (int it = 0; it < 16; it++) issue_one(0, 0, it);
    CP_COMMIT();

    for (int i = 0; i < nk; i++) {
        CP_WAIT(0);
        __syncthreads();

        const __half* sA = gs + (i & 1) * Q_GSTG;
        const __half* sB = sA + Q_GTSZ;
        const bool pre   = (i + 1 < nk);
        const int  snxt  = (i + 1) & 1;
        const int  knxt  = (i + 1) * 64;

#pragma unroll
        for (int ksi = 0; ksi < 4; ksi++) {
            const int ks = ksi * 16;
            uint32_t af[4][4];
#pragma unroll
            for (int mt = 0; mt < 4; mt++) {
                int mrow = wm * 64 + mt * 16 + lm_row;
                ldsm_x4(af[mt][0], af[mt][1], af[mt][2], af[mt][3],
                        smem_u32(sA + mrow*Q_GSK + ks + lm_kc));
            }
            if (pre) {
                issue_one(snxt, knxt, 4*ksi + 0);
                issue_one(snxt, knxt, 4*ksi + 1);
                issue_one(snxt, knxt, 4*ksi + 2);
                issue_one(snxt, knxt, 4*ksi + 3);
            }
#pragma unroll
            for (int p = 0; p < 4; p++) {
                uint32_t b0, b1, b2, b3;
                int nrow = wn * 64 + p * 16 + lm_row;
                ldsm_x4(b0, b1, b2, b3, smem_u32(sB + nrow*Q_GSK + ks + lm_kc));
#pragma unroll
                for (int mt = 0; mt < 4; mt++) {
                    mma_fp16(c[mt][2*p],   af[mt][0], af[mt][1], af[mt][2], af[mt][3], b0, b2);
                    mma_fp16(c[mt][2*p+1], af[mt][0], af[mt][1], af[mt][2], af[mt][3], b1, b3);
                }
            }
        }
        if (pre) CP_COMMIT();
    }

    // epilogue: qkv scatter
    const int lrow = lane >> 2;
    const int lcol = (lane & 3) << 1;
    const float qscale = 0.08838834764831845f * 1.4426950408889634f;
#pragma unroll
    for (int mt = 0; mt < 4; mt++) {
        int mbase = m0 + wm * 64 + mt * 16 + lrow;
#pragma unroll
        for (int nt = 0; nt < 8; nt++) {
            int nbase = n0 + wn * 64 + nt * 8 + lcol;
#pragma unroll
            for (int sI = 0; sI < 2; sI++) {
                int m = mbase + sI * 8;
                float v0 = c[mt][nt][sI*2 + 0];
                float v1 = c[mt][nt][sI*2 + 1];
                int bb = m >> 11;
                int t  = m & 2047;
                int which = nbase >> 11;
                int cidx  = nbase & 2047;
                int h     = cidx >> 7;
                int d     = cidx & 127;
                size_t idx = (((size_t)(bb * HH + h)) * TT + t) * HD + d;
                if (which == 0) { v0 *= qscale; v1 *= qscale; }
                __half2 p = __floats2half2_rn(v0, v1);
                __half* dst = (which == 0) ? q16 : ((which == 1) ? k16 : v16);
                *(uint32_t*)&dst[idx] = *(uint32_t*)&p;
            }
        }
    }
}

// ---------------------------------------------------------------------------
// Output-projection GEMM (proven round-12 kernel): 8 warps, warp tile 64x32,
// block 128x128x64, 3-stage cp.async, one sync/chunk, interleaved prefetch.
// ---------------------------------------------------------------------------
#define GSK 72
#define GTSZ (128*GSK)
#define GSTG (2*GTSZ)
#define G_SMEM (3*GSTG*2)             // 110592 bytes

__global__ __launch_bounds__(256, 2)
void gemm_proj(const __half* __restrict__ A, const __half* __restrict__ W,
               float* __restrict__ fout, const float* __restrict__ bias)
{
    extern __shared__ __half gs[];
    const int Kd = K1, Nd = CC;
    const int tid  = threadIdx.x;
    const int lane = tid & 31;
    const int wid  = tid >> 5;
    const int wm   = wid >> 2;
    const int wn   = wid & 3;
    const int m0   = blockIdx.y * 128;
    const int n0   = blockIdx.x * 128;

    float c[4][4][4];
#pragma unroll
    for (int mt = 0; mt < 4; mt++)
#pragma unroll
        for (int nt = 0; nt < 4; nt++)
#pragma unroll
            for (int r = 0; r < 4; r++) c[mt][nt][r] = 0.0f;

    const int lm_row = lane & 15;
    const int lm_kc  = (lane >> 4) << 3;

    auto issue_one = [&](int s, int kt, int it) {
        __half* stg = gs + s * GSTG;
        int g   = tid + it * 256;
        int sel = g >> 10;
        int rem = g & 1023;
        int row = rem >> 3;
        int col = (rem & 7) * 8;
        const __half* src = (sel == 0) ? (A + (size_t)(m0 + row) * Kd + kt + col)
                                       : (W + (size_t)(n0 + row) * Kd + kt + col);
        cp16(smem_u32(stg + sel * GTSZ + row * GSK + col), src);
    };
    auto issue_all = [&](int s, int kt) {
#pragma unroll
        for (int it = 0; it < 8; it++) issue_one(s, kt, it);
    };

    const int nk = Kd / 64;
    issue_all(0, 0);  CP_COMMIT();
    issue_all(1, 64); CP_COMMIT();

    for (int i = 0; i < nk; i++) {
        if (i + 1 < nk) { CP_WAIT(1); } else { CP_WAIT(0); }
        __syncthreads();

        const __half* sA = gs + (i % 3) * GSTG;
        const __half* sB = sA + GTSZ;
        const bool pre   = (i + 2 < nk);
        const int  snxt  = (i + 2) % 3;
        const int  knxt  = (i + 2) * 64;

#pragma unroll
        for (int ksi = 0; ksi < 4; ksi++) {
            const int ks = ksi * 16;
            uint32_t b[4][2];
#pragma unroll
            for (int p = 0; p < 2; p++) {
                uint32_t r0, r1, r2, r3;
                int nrow = wn * 32 + p * 16 + lm_row;
                ldsm_x4(r0, r1, r2, r3, smem_u32(sB + nrow*GSK + ks + lm_kc));
                b[2*p][0] = r0; b[2*p+1][0] = r1;
                b[2*p][1] = r2; b[2*p+1][1] = r3;
            }
            if (pre) { issue_one(snxt, knxt, 2*ksi); issue_one(snxt, knxt, 2*ksi + 1); }
#pragma unroll
            for (int mt = 0; mt < 4; mt++) {
                uint32_t a0, a1, a2, a3;
                int mrow = wm * 64 + mt * 16 + lm_row;
                ldsm_x4(a0, a1, a2, a3, smem_u32(sA + mrow*GSK + ks + lm_kc));
#pragma unroll
                for (int nt = 0; nt < 4; nt++)
                    mma_fp16(c[mt][nt], a0, a1, a2, a3, b[nt][0], b[nt][1]);
            }
        }
        if (pre) CP_COMMIT();
    }

    const int lrow = lane >> 2;
    const int lcol = (lane & 3) << 1;
#pragma unroll
    for (int mt = 0; mt < 4; mt++) {
        int mbase = m0 + wm * 64 + mt * 16 + lrow;
#pragma unroll
        for (int nt = 0; nt < 4; nt++) {
            int nbase = n0 + wn * 32 + nt * 8 + lcol;
#pragma unroll
            for (int sI = 0; sI < 2; sI++) {
                int m = mbase + sI * 8;
                float2 w;
                w.x = c[mt][nt][sI*2 + 0] + bias[nbase];
                w.y = c[mt][nt][sI*2 + 1] + bias[nbase + 1];
                *(float2*)&fout[(size_t)m * Nd + nbase] = w;
            }
        }
    }
}

// ---------------------------------------------------------------------------
// Flash attention (mma.sync fp16, single-term), causal. BQ=128, BKV=128,
// 8 warps, 3-stage cp.async KV ring (ONE sync per jt), Q in registers.
// exp2-domain softmax. Output y fp16.
// ---------------------------------------------------------------------------
#define FSTR 136
#define FL_TILE (128*FSTR)
#define FL_STG  (2*FL_TILE)
#define FLASH_SMEM (3*FL_STG*2)   // 208896 bytes

__global__ __launch_bounds__(256, 1)
void flash_mma(const __half* __restrict__ q16,
               const __half* __restrict__ k16, const __half* __restrict__ v16,
               __half* __restrict__ y16)
{
    extern __shared__ __half fs[];

    const int qt  = gridDim.x - 1 - blockIdx.x;
    const int bh  = blockIdx.y;
    const int tid = threadIdx.x;
    const int lane = tid & 31;
    const int w    = tid >> 5;

    const size_t base = (size_t)bh * TT * HD;

    auto issue_kv = [&](int s, int jt) {
        __half* sbase = fs + s * FL_STG;
#pragma unroll
        for (int it = 0; it < 16; it++) {
            int g   = tid + it * 256;
            int sel = g >> 11;
            int rem = g & 2047;
            int row = rem >> 4;
            int c8  = (rem & 15) * 8;
            const __half* src = sel ? v16 : k16;
            cp16(smem_u32(sbase + sel * FL_TILE + row * FSTR + c8),
                 src + base + (size_t)(jt * 128 + row) * HD + c8);
        }
    };

    // stage Q through smem, capture to registers
#pragma unroll
    for (int it = 0; it < 4; it++) {
        int idx = tid + it * 256;
        int r   = idx >> 3;
        int c8  = (idx & 7) * 16;
        size_t g = base + (size_t)(qt * 128 + r) * HD + c8;
        *(uint4*)&fs[r * FSTR + c8]     = *(const uint4*)&q16[g];
        *(uint4*)&fs[r * FSTR + c8 + 8] = *(const uint4*)&q16[g + 8];
    }
    __syncthreads();

    const int lm_row = lane & 15;
    const int lm_kc  = (lane >> 4) << 3;
    const int row0   = qt * 128 + w * 16 + (lane >> 2);

    uint32_t qf[8][4];
#pragma unroll
    for (int kc = 0; kc < 8; kc++) {
        int qrow = w * 16 + lm_row;
        ldsm_x4(qf[kc][0], qf[kc][1], qf[kc][2], qf[kc][3],
                smem_u32(fs + qrow*FSTR + kc*16 + lm_kc));
    }
    __syncthreads();

    const int nkt = qt + 1;
    issue_kv(0, 0);                 CP_COMMIT();
    if (nkt > 1) { issue_kv(1, 1);  CP_COMMIT(); }

    float m0 = -1e30f, m1 = -1e30f, l0 = 0.0f, l1 = 0.0f;
    float co[16][4];
#pragma unroll
    for (int dt = 0; dt < 16; dt++)
#pragma unroll
        for (int r = 0; r < 4; r++) co[dt][r] = 0.0f;

    for (int jt = 0; jt < nkt; jt++) {
        if (jt + 1 < nkt) { CP_WAIT(1); } else { CP_WAIT(0); }
        __syncthreads();
        if (jt + 2 < nkt) { issue_kv((jt + 2) % 3, jt + 2); CP_COMMIT(); }

        const __half* Ks = fs + (jt % 3) * FL_STG;
        const __half* Vs = Ks + FL_TILE;

        float s[16][4];
#pragma unroll
        for (int nt = 0; nt < 16; nt++)
#pragma unroll
            for (int r = 0; r < 4; r++) s[nt][r] = 0.0f;

#pragma unroll
        for (int kc = 0; kc < 8; kc++) {
#pragma unroll
            for (int p = 0; p < 8; p++) {
                uint32_t r0, r1, r2, r3;
                int krow = p * 16 + lm_row;
                ldsm_x4(r0, r1, r2, r3, smem_u32(Ks + krow*FSTR + kc*16 + lm_kc));
                mma_fp16(s[2*p],   qf[kc][0], qf[kc][1], qf[kc][2], qf[kc][3], r0, r2);
                mma_fp16(s[2*p+1], qf[kc][0], qf[kc][1], qf[kc][2], qf[kc][3], r1, r3);
            }
        }

        if (jt == qt) {
#pragma unroll
            for (int nt = 0; nt < 16; nt++) {
                int colb = jt * 128 + nt * 8 + (lane & 3) * 2;
#pragma unroll
                for (int e = 0; e < 2; e++) {
                    if (colb + e > row0)     s[nt][e]     = -1e30f;
                    if (colb + e > row0 + 8) s[nt][2 + e] = -1e30f;
                }
            }
        }

        float mx0 = -1e30f, mx1 = -1e30f;
#pragma unroll
        for (int nt = 0; nt < 16; nt++) {
            mx0 = fmaxf(mx0, fmaxf(s[nt][0], s[nt][1]));
            mx1 = fmaxf(mx1, fmaxf(s[nt][2], s[nt][3]));
        }
        mx0 = fmaxf(mx0, __shfl_xor_sync(0xffffffffu, mx0, 1));
        mx0 = fmaxf(mx0, __shfl_xor_sync(0xffffffffu, mx0, 2));
        mx1 = fmaxf(mx1, __shfl_xor_sync(0xffffffffu, mx1, 1));
        mx1 = fmaxf(mx1, __shfl_xor_sync(0xffffffffu, mx1, 2));

        float mn0 = fmaxf(m0, mx0);
        float mn1 = fmaxf(m1, mx1);
        float cr0 = exp2f(m0 - mn0);
        float cr1 = exp2f(m1 - mn1);
        m0 = mn0; m1 = mn1;

        float rs0 = 0.0f, rs1 = 0.0f;
#pragma unroll
        for (int nt = 0; nt < 16; nt++) {
            s[nt][0] = exp2f(s[nt][0] - mn0);
            s[nt][1] = exp2f(s[nt][1] - mn0);
            s[nt][2] = exp2f(s[nt][2] - mn1);
            s[nt][3] = exp2f(s[nt][3] - mn1);
            rs0 += s[nt][0] + s[nt][1];
            rs1 += s[nt][2] + s[nt][3];
        }
        rs0 += __shfl_xor_sync(0xffffffffu, rs0, 1);
        rs0 += __shfl_xor_sync(0xffffffffu, rs0, 2);
        rs1 += __shfl_xor_sync(0xffffffffu, rs1, 1);
        rs1 += __shfl_xor_sync(0xffffffffu, rs1, 2);
        l0 = l0 * cr0 + rs0;
        l1 = l1 * cr1 + rs1;

#pragma unroll
        for (int dt = 0; dt < 16; dt++) {
            co[dt][0] *= cr0; co[dt][1] *= cr0;
            co[dt][2] *= cr1; co[dt][3] *= cr1;
        }

#pragma unroll
        for (int kc2 = 0; kc2 < 8; kc2++) {
            __half2 hp;
            uint32_t p0, p1, p2, p3;
            hp = __floats2half2_rn(s[2*kc2][0],   s[2*kc2][1]);   p0 = *(uint32_t*)&hp;
            hp = __floats2half2_rn(s[2*kc2][2],   s[2*kc2][3]);   p1 = *(uint32_t*)&hp;
            hp = __floats2half2_rn(s[2*kc2+1][0], s[2*kc2+1][1]); p2 = *(uint32_t*)&hp;
            hp = __floats2half2_rn(s[2*kc2+1][2], s[2*kc2+1][3]); p3 = *(uint32_t*)&hp;
#pragma unroll
            for (int dp = 0; dp < 8; dp++) {
                uint32_t v0, v1, v2, v3;
                int vrow = kc2 * 16 + lm_row;
                ldsm_x4t(v0, v1, v2, v3, smem_u32(Vs + vrow*FSTR + dp*16 + lm_kc));
                mma_fp16(co[2*dp],   p0, p1, p2, p3, v0, v1);
                mma_fp16(co[2*dp+1], p0, p1, p2, p3, v2, v3);
            }
        }
    }

    const float inv0 = 1.0f / l0;
    const float inv1 = 1.0f / l1;
    const int b = bh >> 4;
    const int h = bh & 15;
#pragma unroll
    for (int dt = 0; dt < 16; dt++) {
        int d = dt * 8 + (lane & 3) * 2;
        size_t i0 = ((size_t)(b * TT + row0)) * CC + h * HD + d;
        __half2 p0 = __floats2half2_rn(co[dt][0] * inv0, co[dt][1] * inv0);
        *(uint32_t*)&y16[i0] = *(uint32_t*)&p0;
        size_t i1 = ((size_t)(b * TT + row0 + 8)) * CC + h * HD + d;
        __half2 p1 = __floats2half2_rn(co[dt][2] * inv1, co[dt][3] * inv1);
        *(uint32_t*)&y16[i1] = *(uint32_t*)&p1;
    }
}

// ---------------------------------------------------------------------------
extern "C" void kernel_launch(void* const* d_in, const int* in_sizes, int n_in,
                              void* d_out, int out_size)
{
    const float* x      = (const float*)d_in[0];
    const float* w_attn = (const float*)d_in[1];
    const float* w_proj = (const float*)d_in[2];
    const float* b_proj = (const float*)d_in[3];
    float* out = (float*)d_out;

    __half *x16, *wa16, *wp16, *y16, *q16, *k16, *v16;
    cudaGetSymbolAddress((void**)&x16,  g_x16);
    cudaGetSymbolAddress((void**)&wa16, g_wa16);
    cudaGetSymbolAddress((void**)&wp16, g_wp16);
    cudaGetSymbolAddress((void**)&q16,  g_q16);
    cudaGetSymbolAddress((void**)&k16,  g_k16);
    cudaGetSymbolAddress((void**)&v16,  g_v16);
    cudaGetSymbolAddress((void**)&y16,  g_y16);

    cudaFuncSetAttribute(gemm_qkv64, cudaFuncAttributeMaxDynamicSharedMemorySize, Q_SMEM);
    cudaFuncSetAttribute(gemm_proj,  cudaFuncAttributeMaxDynamicSharedMemorySize, G_SMEM);
    cudaFuncSetAttribute(flash_mma,  cudaFuncAttributeMaxDynamicSharedMemorySize, FLASH_SMEM);

    const int total4 = XN4 + WAN4 + WPN4;
    split_all<<<(total4 + 255)/256, 256>>>(x, w_attn, w_proj,
        (uint2*)x16, (uint2*)wa16, (uint2*)wp16);

    gemm_qkv64<<<dim3(N1/128, M1/128), 128, Q_SMEM>>>(x16, wa16, q16, k16, v16);

    flash_mma<<<dim3(TT/128, BB*HH), 256, FLASH_SMEM>>>(q16, k16, v16, y16);

    gemm_proj<<<dim3(CC/128, M1/128), 256, G_SMEM>>>(y16, wp16, out, b_proj);
}

// round 15
// speedup vs baseline: 1.1595x; 1.1595x over previous
#include <cuda_runtime.h>
#include <cuda_fp16.h>
#include <cstdint>

#define BB 2
#define TT 2048
#define CC 2048
#define HH 16
#define HD 128
#define M1 (BB*TT)      // 4096
#define N1 (3*CC)       // 6144
#define K1 CC           // 2048

// ---------------- device scratch ----------------
__device__ __half g_x16[M1*K1];
__device__ __half g_wa16[N1*K1];
__device__ __half g_wp16[CC*CC];
__device__ __half g_q16[BB*HH*TT*HD];
__device__ __half g_k16[BB*HH*TT*HD];
__device__ __half g_v16[BB*HH*TT*HD];
__device__ __half g_y16[M1*CC];

// ---------------- helpers ----------------
__device__ __forceinline__ uint32_t smem_u32(const void* p) {
    return (uint32_t)__cvta_generic_to_shared(p);
}
__device__ __forceinline__ void ldsm_x4(uint32_t& r0, uint32_t& r1,
                                        uint32_t& r2, uint32_t& r3, uint32_t addr) {
    asm volatile("ldmatrix.sync.aligned.m8n8.x4.shared.b16 {%0,%1,%2,%3}, [%4];\n"
                 : "=r"(r0), "=r"(r1), "=r"(r2), "=r"(r3) : "r"(addr));
}
__device__ __forceinline__ void ldsm_x4t(uint32_t& r0, uint32_t& r1,
                                         uint32_t& r2, uint32_t& r3, uint32_t addr) {
    asm volatile("ldmatrix.sync.aligned.m8n8.x4.trans.shared.b16 {%0,%1,%2,%3}, [%4];\n"
                 : "=r"(r0), "=r"(r1), "=r"(r2), "=r"(r3) : "r"(addr));
}
__device__ __forceinline__ void mma_fp16(float* c,
                                         uint32_t a0, uint32_t a1, uint32_t a2, uint32_t a3,
                                         uint32_t b0, uint32_t b1) {
    asm volatile("mma.sync.aligned.m16n8k16.row.col.f32.f16.f16.f32 "
                 "{%0,%1,%2,%3}, {%4,%5,%6,%7}, {%8,%9}, {%0,%1,%2,%3};\n"
                 : "+f"(c[0]), "+f"(c[1]), "+f"(c[2]), "+f"(c[3])
                 : "r"(a0), "r"(a1), "r"(a2), "r"(a3), "r"(b0), "r"(b1));
}
__device__ __forceinline__ void cp16(uint32_t saddr, const void* g) {
    asm volatile("cp.async.cg.shared.global [%0], [%1], 16;\n" :: "r"(saddr), "l"(g));
}
#define CP_COMMIT() asm volatile("cp.async.commit_group;\n" ::: "memory")
#define CP_WAIT(N)  asm volatile("cp.async.wait_group %0;\n" :: "n"(N) : "memory")

// ---------------- fused fp32 -> fp16 cast (all three inputs) ----------------
#define XN4  (M1*K1/4)
#define WAN4 (N1*K1/4)
#define WPN4 (CC*CC/4)

__global__ void split_all(const float* __restrict__ x, const float* __restrict__ wa,
                          const float* __restrict__ wp,
                          uint2* __restrict__ ox, uint2* __restrict__ owa,
                          uint2* __restrict__ owp)
{
    int i = blockIdx.x * blockDim.x + threadIdx.x;
    const float* src;
    uint2* dst;
    int j;
    if (i < XN4)                 { src = x;  dst = ox;  j = i; }
    else if (i < XN4 + WAN4)     { src = wa; dst = owa; j = i - XN4; }
    else if (i < XN4+WAN4+WPN4)  { src = wp; dst = owp; j = i - XN4 - WAN4; }
    else return;
    float4 v = ((const float4*)src)[j];
    __half2 h0 = __floats2half2_rn(v.x, v.y);
    __half2 h1 = __floats2half2_rn(v.z, v.w);
    uint2 o;
    o.x = *(uint32_t*)&h0;
    o.y = *(uint32_t*)&h1;
    dst[j] = o;
}

// ---------------------------------------------------------------------------
// 1-term fp16 GEMM: C = A(MxK) * W(NxK)^T, fp32 accumulate.
// Block 128x128x64, 8 warps (2x4), warp tile 64x32, 3-stage cp.async,
// ONE __syncthreads per K-chunk; prefetch interleaved; ALL load addresses
// precomputed outside the K-loop (only kt varies).
// EPI 0: qkv scatter (q scaled by scale*log2e, fp16; k,v fp16);
// EPI 1: fp32 out + bias.
// ---------------------------------------------------------------------------
#define GSK 72
#define GTSZ (128*GSK)
#define GSTG (2*GTSZ)                 // A + B per stage (18432 halves)
#define G_SMEM (3*GSTG*2)             // 110592 bytes

template<int EPI>
__global__ __launch_bounds__(256, 2)
void gemm_fp16(const __half* __restrict__ A, const __half* __restrict__ W,
               int Kd, int Nd,
               __half* q16, __half* k16, __half* v16,
               float* fout, const float* __restrict__ bias)
{
    extern __shared__ __half gs[];

    const int tid  = threadIdx.x;
    const int lane = tid & 31;
    const int wid  = tid >> 5;
    const int wm   = wid >> 2;      // 0..1
    const int wn   = wid & 3;       // 0..3
    const int m0   = blockIdx.y * 128;
    const int n0   = blockIdx.x * 128;

    float c[4][4][4];
#pragma unroll
    for (int mt = 0; mt < 4; mt++)
#pragma unroll
        for (int nt = 0; nt < 4; nt++)
#pragma unroll
            for (int r = 0; r < 4; r++) c[mt][nt][r] = 0.0f;

    const int lm_row = lane & 15;
    const int lm_kc  = (lane >> 4) << 3;

    // precompute cp.async source element offsets + smem offsets (loop-invariant)
    uint32_t goff[8], soff[8];
#pragma unroll
    for (int it = 0; it < 8; it++) {
        int g   = tid + it * 256;       // 0..2047
        int sel = g >> 10;              // 0=A (it<4), 1=W (it>=4)
        int rem = g & 1023;
        int row = rem >> 3;             // 0..127
        int col = (rem & 7) * 8;        // 0..56
        goff[it] = (uint32_t)((sel ? (n0 + row) : (m0 + row)) * Kd + col);
        soff[it] = (uint32_t)(sel * GTSZ + row * GSK + col);
    }

    auto issue_one = [&](int s, int kt, int it) {
        const __half* src = ((it < 4) ? A : W) + goff[it] + kt;
        cp16(smem_u32(gs + s * GSTG + soff[it]), src);
    };
    auto issue_all = [&](int s, int kt) {
#pragma unroll
        for (int it = 0; it < 8; it++) issue_one(s, kt, it);
    };

    const int nk = Kd / 64;
    issue_all(0, 0);  CP_COMMIT();
    issue_all(1, 64); CP_COMMIT();

    for (int i = 0; i < nk; i++) {
        if (i + 1 < nk) { CP_WAIT(1); } else { CP_WAIT(0); }
        __syncthreads();

        const __half* sA = gs + (i % 3) * GSTG;
        const __half* sB = sA + GTSZ;
        const bool pre   = (i + 2 < nk);
        const int  snxt  = (i + 2) % 3;
        const int  knxt  = (i + 2) * 64;

#pragma unroll
        for (int ksi = 0; ksi < 4; ksi++) {
            const int ks = ksi * 16;
            uint32_t b[4][2];
#pragma unroll
            for (int p = 0; p < 2; p++) {
                uint32_t r0, r1, r2, r3;
                int nrow = wn * 32 + p * 16 + lm_row;
                ldsm_x4(r0, r1, r2, r3, smem_u32(sB + nrow*GSK + ks + lm_kc));
                b[2*p][0] = r0; b[2*p+1][0] = r1;
                b[2*p][1] = r2; b[2*p+1][1] = r3;
            }
            // interleave 2 of the 8 prefetch cp.asyncs per ks step
            if (pre) { issue_one(snxt, knxt, 2*ksi); issue_one(snxt, knxt, 2*ksi + 1); }
#pragma unroll
            for (int mt = 0; mt < 4; mt++) {
                uint32_t a0, a1, a2, a3;
                int mrow = wm * 64 + mt * 16 + lm_row;
                ldsm_x4(a0, a1, a2, a3, smem_u32(sA + mrow*GSK + ks + lm_kc));
#pragma unroll
                for (int nt = 0; nt < 4; nt++)
                    mma_fp16(c[mt][nt], a0, a1, a2, a3, b[nt][0], b[nt][1]);
            }
        }
        if (pre) CP_COMMIT();
    }

    // epilogue
    const int lrow = lane >> 2;
    const int lcol = (lane & 3) << 1;
    // 1/sqrt(128) * log2(e): folded so flash can use exp2
    const float qscale = 0.08838834764831845f * 1.4426950408889634f;
#pragma unroll
    for (int mt = 0; mt < 4; mt++) {
        int mbase = m0 + wm * 64 + mt * 16 + lrow;
#pragma unroll
        for (int nt = 0; nt < 4; nt++) {
            int nbase = n0 + wn * 32 + nt * 8 + lcol;
#pragma unroll
            for (int sI = 0; sI < 2; sI++) {
                int m = mbase + sI * 8;
                float v0 = c[mt][nt][sI*2 + 0];
                float v1 = c[mt][nt][sI*2 + 1];
                if (EPI == 0) {
                    int bb = m >> 11;
                    int t  = m & 2047;
                    int which = nbase >> 11;
                    int cidx  = nbase & 2047;
                    int h     = cidx >> 7;
                    int d     = cidx & 127;
                    size_t idx = (((size_t)(bb * HH + h)) * TT + t) * HD + d;
                    if (which == 0) { v0 *= qscale; v1 *= qscale; }
                    __half2 p = __floats2half2_rn(v0, v1);
                    __half* dst = (which == 0) ? q16 : ((which == 1) ? k16 : v16);
                    *(uint32_t*)&dst[idx] = *(uint32_t*)&p;
                } else {
                    float2 w;
                    w.x = v0 + bias[nbase];
                    w.y = v1 + bias[nbase + 1];
                    *(float2*)&fout[(size_t)m * Nd + nbase] = w;
                }
            }
        }
    }
}

// ---------------------------------------------------------------------------
// Flash attention (mma.sync fp16, single-term), causal. BQ=128, BKV=128,
// 8 warps, 3-stage cp.async KV ring (ONE sync per jt), Q in registers,
// KV load addresses precomputed. exp2-domain softmax. Output y fp16.
// ---------------------------------------------------------------------------
#define FSTR 136
#define FL_TILE (128*FSTR)
#define FL_STG  (2*FL_TILE)
#define FLASH_SMEM (3*FL_STG*2)   // 208896 bytes

__global__ __launch_bounds__(256, 1)
void flash_mma(const __half* __restrict__ q16,
               const __half* __restrict__ k16, const __half* __restrict__ v16,
               __half* __restrict__ y16)
{
    extern __shared__ __half fs[];   // 3-stage KV ring; stage 0 doubles as Q staging

    const int qt  = gridDim.x - 1 - blockIdx.x;   // heavy tiles first
    const int bh  = blockIdx.y;
    const int tid = threadIdx.x;
    const int lane = tid & 31;
    const int w    = tid >> 5;

    const size_t base = (size_t)bh * TT * HD;

    // precompute KV cp.async offsets (loop-invariant in jt)
    uint32_t kvg[16], kvs[16];
#pragma unroll
    for (int it = 0; it < 16; it++) {
        int g   = tid + it * 256;     // 0..4095
        int sel = g >> 11;            // 0=K (it<8), 1=V (it>=8)
        int rem = g & 2047;
        int row = rem >> 4;           // 0..127
        int c8  = (rem & 15) * 8;
        kvg[it] = (uint32_t)(row * HD + c8);
        kvs[it] = (uint32_t)(sel * FL_TILE + row * FSTR + c8);
    }

    auto issue_kv = [&](int s, int jt) {
        const size_t jb = base + (size_t)jt * 128 * HD;
#pragma unroll
        for (int it = 0; it < 16; it++) {
            const __half* src = ((it < 8) ? k16 : v16) + jb + kvg[it];
            cp16(smem_u32(fs + s * FL_STG + kvs[it]), src);
        }
    };

    // ---- stage Q through smem (ring stage 0 region), capture to registers ----
#pragma unroll
    for (int it = 0; it < 4; it++) {
        int idx = tid + it * 256;
        int r   = idx >> 3;
        int c8  = (idx & 7) * 16;
        size_t g = base + (size_t)(qt * 128 + r) * HD + c8;
        *(uint4*)&fs[r * FSTR + c8]     = *(const uint4*)&q16[g];
        *(uint4*)&fs[r * FSTR + c8 + 8] = *(const uint4*)&q16[g + 8];
    }
    __syncthreads();

    const int lm_row = lane & 15;
    const int lm_kc  = (lane >> 4) << 3;
    const int row0   = qt * 128 + w * 16 + (lane >> 2);

    uint32_t qf[8][4];
#pragma unroll
    for (int kc = 0; kc < 8; kc++) {
        int qrow = w * 16 + lm_row;
        ldsm_x4(qf[kc][0], qf[kc][1], qf[kc][2], qf[kc][3],
                smem_u32(fs + qrow*FSTR + kc*16 + lm_kc));
    }
    __syncthreads();   // all warps captured Q before KV cp.async overwrites stage 0

    const int nkt = qt + 1;
    issue_kv(0, 0);                 CP_COMMIT();
    if (nkt > 1) { issue_kv(1, 1);  CP_COMMIT(); }

    float m0 = -1e30f, m1 = -1e30f, l0 = 0.0f, l1 = 0.0f;
    float co[16][4];
#pragma unroll
    for (int dt = 0; dt < 16; dt++)
#pragma unroll
        for (int r = 0; r < 4; r++) co[dt][r] = 0.0f;

    for (int jt = 0; jt < nkt; jt++) {
        if (jt + 1 < nkt) { CP_WAIT(1); } else { CP_WAIT(0); }
        __syncthreads();
        if (jt + 2 < nkt) { issue_kv((jt + 2) % 3, jt + 2); CP_COMMIT(); }

        const __half* Ks = fs + (jt % 3) * FL_STG;
        const __half* Vs = Ks + FL_TILE;

        float s[16][4];
#pragma unroll
        for (int nt = 0; nt < 16; nt++)
#pragma unroll
            for (int r = 0; r < 4; r++) s[nt][r] = 0.0f;

#pragma unroll
        for (int kc = 0; kc < 8; kc++) {
#pragma unroll
            for (int p = 0; p < 8; p++) {
                uint32_t r0, r1, r2, r3;
                int krow = p * 16 + lm_row;
                ldsm_x4(r0, r1, r2, r3, smem_u32(Ks + krow*FSTR + kc*16 + lm_kc));
                mma_fp16(s[2*p],   qf[kc][0], qf[kc][1], qf[kc][2], qf[kc][3], r0, r2);
                mma_fp16(s[2*p+1], qf[kc][0], qf[kc][1], qf[kc][2], qf[kc][3], r1, r3);
            }
        }

        if (jt == qt) {
#pragma unroll
            for (int nt = 0; nt < 16; nt++) {
                int colb = jt * 128 + nt * 8 + (lane & 3) * 2;
#pragma unroll
                for (int e = 0; e < 2; e++) {
                    if (colb + e > row0)     s[nt][e]     = -1e30f;
                    if (colb + e > row0 + 8) s[nt][2 + e] = -1e30f;
                }
            }
        }

        float mx0 = -1e30f, mx1 = -1e30f;
#pragma unroll
        for (int nt = 0; nt < 16; nt++) {
            mx0 = fmaxf(mx0, fmaxf(s[nt][0], s[nt][1]));
            mx1 = fmaxf(mx1, fmaxf(s[nt][2], s[nt][3]));
        }
        mx0 = fmaxf(mx0, __shfl_xor_sync(0xffffffffu, mx0, 1));
        mx0 = fmaxf(mx0, __shfl_xor_sync(0xffffffffu, mx0, 2));
        mx1 = fmaxf(mx1, __shfl_xor_sync(0xffffffffu, mx1, 1));
        mx1 = fmaxf(mx1, __shfl_xor_sync(0xffffffffu, mx1, 2));

        float mn0 = fmaxf(m0, mx0);
        float mn1 = fmaxf(m1, mx1);
        float cr0 = exp2f(m0 - mn0);
        float cr1 = exp2f(m1 - mn1);
        m0 = mn0; m1 = mn1;

        float rs0 = 0.0f, rs1 = 0.0f;
#pragma unroll
        for (int nt = 0; nt < 16; nt++) {
            s[nt][0] = exp2f(s[nt][0] - mn0);
            s[nt][1] = exp2f(s[nt][1] - mn0);
            s[nt][2] = exp2f(s[nt][2] - mn1);
            s[nt][3] = exp2f(s[nt][3] - mn1);
            rs0 += s[nt][0] + s[nt][1];
            rs1 += s[nt][2] + s[nt][3];
        }
        rs0 += __shfl_xor_sync(0xffffffffu, rs0, 1);
        rs0 += __shfl_xor_sync(0xffffffffu, rs0, 2);
        rs1 += __shfl_xor_sync(0xffffffffu, rs1, 1);
        rs1 += __shfl_xor_sync(0xffffffffu, rs1, 2);
        l0 = l0 * cr0 + rs0;
        l1 = l1 * cr1 + rs1;

#pragma unroll
        for (int dt = 0; dt < 16; dt++) {
            co[dt][0] *= cr0; co[dt][1] *= cr0;
            co[dt][2] *= cr1; co[dt][3] *= cr1;
        }

        // O += P V (P,V single fp16)
#pragma unroll
        for (int kc2 = 0; kc2 < 8; kc2++) {
            __half2 hp;
            uint32_t p0, p1, p2, p3;
            hp = __floats2half2_rn(s[2*kc2][0],   s[2*kc2][1]);   p0 = *(uint32_t*)&hp;
            hp = __floats2half2_rn(s[2*kc2][2],   s[2*kc2][3]);   p1 = *(uint32_t*)&hp;
            hp = __floats2half2_rn(s[2*kc2+1][0], s[2*kc2+1][1]); p2 = *(uint32_t*)&hp;
            hp = __floats2half2_rn(s[2*kc2+1][2], s[2*kc2+1][3]); p3 = *(uint32_t*)&hp;
#pragma unroll
            for (int dp = 0; dp < 8; dp++) {
                uint32_t v0, v1, v2, v3;
                int vrow = kc2 * 16 + lm_row;
                ldsm_x4t(v0, v1, v2, v3, smem_u32(Vs + vrow*FSTR + dp*16 + lm_kc));
                mma_fp16(co[2*dp],   p0, p1, p2, p3, v0, v1);
                mma_fp16(co[2*dp+1], p0, p1, p2, p3, v2, v3);
            }
        }
    }

    const float inv0 = 1.0f / l0;
    const float inv1 = 1.0f / l1;
    const int b = bh >> 4;
    const int h = bh & 15;
#pragma unroll
    for (int dt = 0; dt < 16; dt++) {
        int d = dt * 8 + (lane & 3) * 2;
        size_t i0 = ((size_t)(b * TT + row0)) * CC + h * HD + d;
        __half2 p0 = __floats2half2_rn(co[dt][0] * inv0, co[dt][1] * inv0);
        *(uint32_t*)&y16[i0] = *(uint32_t*)&p0;
        size_t i1 = ((size_t)(b * TT + row0 + 8)) * CC + h * HD + d;
        __half2 p1 = __floats2half2_rn(co[dt][2] * inv1, co[dt][3] * inv1);
        *(uint32_t*)&y16[i1] = *(uint32_t*)&p1;
    }
}

// ---------------------------------------------------------------------------
extern "C" void kernel_launch(void* const* d_in, const int* in_sizes, int n_in,
                              void* d_out, int out_size)
{
    const float* x      = (const float*)d_in[0];
    const float* w_attn = (const float*)d_in[1];
    const float* w_proj = (const float*)d_in[2];
    const float* b_proj = (const float*)d_in[3];
    float* out = (float*)d_out;

    __half *x16, *wa16, *wp16, *y16, *q16, *k16, *v16;
    cudaGetSymbolAddress((void**)&x16,  g_x16);
    cudaGetSymbolAddress((void**)&wa16, g_wa16);
    cudaGetSymbolAddress((void**)&wp16, g_wp16);
    cudaGetSymbolAddress((void**)&q16,  g_q16);
    cudaGetSymbolAddress((void**)&k16,  g_k16);
    cudaGetSymbolAddress((void**)&v16,  g_v16);
    cudaGetSymbolAddress((void**)&y16,  g_y16);

    cudaFuncSetAttribute(gemm_fp16<0>, cudaFuncAttributeMaxDynamicSharedMemorySize, G_SMEM);
    cudaFuncSetAttribute(gemm_fp16<1>, cudaFuncAttributeMaxDynamicSharedMemorySize, G_SMEM);
    cudaFuncSetAttribute(flash_mma,    cudaFuncAttributeMaxDynamicSharedMemorySize, FLASH_SMEM);

    const int total4 = XN4 + WAN4 + WPN4;
    split_all<<<(total4 + 255)/256, 256>>>(x, w_attn, w_proj,
        (uint2*)x16, (uint2*)wa16, (uint2*)wp16);

    gemm_fp16<0><<<dim3(N1/128, M1/128), 256, G_SMEM>>>(
        x16, wa16, K1, N1, q16, k16, v16, nullptr, nullptr);

    flash_mma<<<dim3(TT/128, BB*HH), 256, FLASH_SMEM>>>(q16, k16, v16, y16);

    gemm_fp16<1><<<dim3(CC/128, M1/128), 256, G_SMEM>>>(
        y16, wp16, K1, CC, nullptr, nullptr, nullptr,
        out, b_proj);
}